// round 1
// baseline (speedup 1.0000x reference)
#include <cuda_runtime.h>
#include <stdint.h>

#define N_NODES 100000
#define N_EDGES 1600000
#define N_GRAPH 64
#define HID 128
#define IN_C 4
#define SCAN_CHUNK 512
#define SCAN_BLKS ((N_NODES + SCAN_CHUNK - 1) / SCAN_CHUNK)   // 196

// ---------------- scratch (static device allocations) ----------------
__device__ float g_bufA[(size_t)N_NODES * HID];   // 51.2 MB
__device__ float g_bufB[(size_t)N_NODES * HID];   // 51.2 MB
__device__ int   g_csr[N_EDGES];
__device__ int   g_deg[N_NODES];
__device__ int   g_off[N_NODES + 1];
__device__ int   g_cur[N_NODES];
__device__ float g_dinv[N_NODES];
__device__ int   g_bsum[SCAN_BLKS];
__device__ int   g_gb[N_GRAPH + 1];
__device__ int   g_is64;

// ---------------- dtype detection ----------------
// If indices are int64, the high 32-bit word of each element is 0 (values < 100000 >= 0).
__global__ void k_detect(const int* ei32) {
    int all0 = 1;
    for (int k = 1; k < 129; k += 2) all0 &= (ei32[k] == 0);
    g_is64 = all0;
}

__device__ __forceinline__ int load_idx(const void* p, long long i) {
    if (g_is64) return (int)((const long long*)p)[i];
    return ((const int*)p)[i];
}

// ---------------- degree count ----------------
__global__ void k_deg(const void* ei) {
    int e = blockIdx.x * blockDim.x + threadIdx.x;
    if (e >= N_EDGES) return;
    int d = load_idx(ei, (long long)N_EDGES + e);
    atomicAdd(&g_deg[d], 1);
}

__global__ void k_dinv() {
    int v = blockIdx.x * blockDim.x + threadIdx.x;
    if (v >= N_NODES) return;
    g_dinv[v] = rsqrtf((float)(g_deg[v] + 1));   // +1 for self loop
}

// ---------------- exclusive scan of degrees -> CSR offsets ----------------
__global__ void k_scan1() {
    __shared__ int s[SCAN_CHUNK];
    int tid = threadIdx.x;
    int i = blockIdx.x * SCAN_CHUNK + tid;
    s[tid] = (i < N_NODES) ? g_deg[i] : 0;
    __syncthreads();
    for (int d = SCAN_CHUNK / 2; d > 0; d >>= 1) {
        if (tid < d) s[tid] += s[tid + d];
        __syncthreads();
    }
    if (tid == 0) g_bsum[blockIdx.x] = s[0];
}

__global__ void k_scan2() {
    __shared__ int s[256];
    int tid = threadIdx.x;
    int v = (tid < SCAN_BLKS) ? g_bsum[tid] : 0;
    s[tid] = v;
    __syncthreads();
    for (int d = 1; d < 256; d <<= 1) {
        int t = (tid >= d) ? s[tid - d] : 0;
        __syncthreads();
        s[tid] += t;
        __syncthreads();
    }
    if (tid < SCAN_BLKS) g_bsum[tid] = s[tid] - v;   // exclusive
}

__global__ void k_scan3() {
    __shared__ int s[SCAN_CHUNK];
    int tid = threadIdx.x;
    int i = blockIdx.x * SCAN_CHUNK + tid;
    int v = (i < N_NODES) ? g_deg[i] : 0;
    s[tid] = v;
    __syncthreads();
    for (int d = 1; d < SCAN_CHUNK; d <<= 1) {
        int t = (tid >= d) ? s[tid - d] : 0;
        __syncthreads();
        s[tid] += t;
        __syncthreads();
    }
    if (i < N_NODES) g_off[i] = g_bsum[blockIdx.x] + s[tid] - v;
    if (i == 0) g_off[N_NODES] = N_EDGES;
}

// ---------------- CSR fill (counting sort by dst) ----------------
__global__ void k_fill(const void* ei) {
    int e = blockIdx.x * blockDim.x + threadIdx.x;
    if (e >= N_EDGES) return;
    int s = load_idx(ei, e);
    int d = load_idx(ei, (long long)N_EDGES + e);
    int pos = g_off[d] + atomicAdd(&g_cur[d], 1);
    g_csr[pos] = s;
}

// ---------------- layer-1 input transform: g0 = dinv * (x @ W1) ----------------
__global__ void k_xw1(const float* __restrict__ x, const float* __restrict__ W1) {
    __shared__ float xs[IN_C];
    int v = blockIdx.x;
    int c = threadIdx.x;
    if (c < IN_C) xs[c] = x[v * IN_C + c];
    __syncthreads();
    float acc = xs[0] * W1[c] + xs[1] * W1[HID + c]
              + xs[2] * W1[2 * HID + c] + xs[3] * W1[3 * HID + c];
    g_bufA[(size_t)v * HID + c] = g_dinv[v] * acc;
}

// ---------------- gather: out[v] = relu(dinv[v]*(sum_in g[src] + g[v]) + b) ----------------
__global__ void k_gather(const float* __restrict__ gin, const float* __restrict__ bias,
                         float* __restrict__ gout) {
    int warp = (blockIdx.x * blockDim.x + threadIdx.x) >> 5;
    int lane = threadIdx.x & 31;
    if (warp >= N_NODES) return;
    int v = warp;
    const float4* gin4 = (const float4*)gin;
    float4 acc = gin4[(size_t)v * 32 + lane];   // self loop term
    int j = g_off[v], e = g_off[v + 1];
    for (; j + 3 < e; j += 4) {
        int i0 = __ldg(&g_csr[j]);
        int i1 = __ldg(&g_csr[j + 1]);
        int i2 = __ldg(&g_csr[j + 2]);
        int i3 = __ldg(&g_csr[j + 3]);
        float4 t0 = __ldg(&gin4[(size_t)i0 * 32 + lane]);
        float4 t1 = __ldg(&gin4[(size_t)i1 * 32 + lane]);
        float4 t2 = __ldg(&gin4[(size_t)i2 * 32 + lane]);
        float4 t3 = __ldg(&gin4[(size_t)i3 * 32 + lane]);
        acc.x += t0.x + t1.x + t2.x + t3.x;
        acc.y += t0.y + t1.y + t2.y + t3.y;
        acc.z += t0.z + t1.z + t2.z + t3.z;
        acc.w += t0.w + t1.w + t2.w + t3.w;
    }
    for (; j < e; ++j) {
        int i0 = __ldg(&g_csr[j]);
        float4 t0 = __ldg(&gin4[(size_t)i0 * 32 + lane]);
        acc.x += t0.x; acc.y += t0.y; acc.z += t0.z; acc.w += t0.w;
    }
    float dv = g_dinv[v];
    float4 bb = ((const float4*)bias)[lane];
    float4 r;
    r.x = fmaxf(dv * acc.x + bb.x, 0.0f);
    r.y = fmaxf(dv * acc.y + bb.y, 0.0f);
    r.z = fmaxf(dv * acc.z + bb.z, 0.0f);
    r.w = fmaxf(dv * acc.w + bb.w, 0.0f);
    ((float4*)gout)[(size_t)v * 32 + lane] = r;
}

// ---------------- dense transform: out = dinv * (hin @ W2)  (128x128) ----------------
// block = 256 threads; tile = 32 rows x 128 cols; thread computes 4x4 micro-tile.
// smem: W2 full (128*128 f32 = 64KB) + transposed h-tile hsT[128][36] (18KB).
#define HT_PITCH 36
__global__ void k_h2w2(const float* __restrict__ hin, const float* __restrict__ W2,
                       float* __restrict__ outp) {
    extern __shared__ float sm[];
    float* W2s = sm;                       // 128*128
    float* hsT = sm + HID * HID;           // [128][HT_PITCH]
    int t = threadIdx.x;
    for (int i = t; i < HID * HID; i += 256) W2s[i] = W2[i];
    int cg = t & 31;   // cols cg*4 .. cg*4+3
    int rg = t >> 5;   // rows rg*4 .. rg*4+3
    const int ntiles = N_NODES / 32;       // 3125
    for (int tile = blockIdx.x; tile < ntiles; tile += gridDim.x) {
        int row0 = tile * 32;
        __syncthreads();                   // also covers initial W2 load
        for (int i = t; i < 32 * HID; i += 256) {
            int r = i >> 7, c = i & 127;
            hsT[c * HT_PITCH + r] = hin[(size_t)(row0 + r) * HID + c];
        }
        __syncthreads();
        float4 a0 = {0,0,0,0}, a1 = {0,0,0,0}, a2 = {0,0,0,0}, a3 = {0,0,0,0};
        #pragma unroll 4
        for (int k = 0; k < HID; ++k) {
            float4 h4 = *(const float4*)&hsT[k * HT_PITCH + rg * 4];
            float4 w  = *(const float4*)&W2s[k * HID + cg * 4];
            a0.x += h4.x * w.x; a0.y += h4.x * w.y; a0.z += h4.x * w.z; a0.w += h4.x * w.w;
            a1.x += h4.y * w.x; a1.y += h4.y * w.y; a1.z += h4.y * w.z; a1.w += h4.y * w.w;
            a2.x += h4.z * w.x; a2.y += h4.z * w.y; a2.z += h4.z * w.z; a2.w += h4.z * w.w;
            a3.x += h4.w * w.x; a3.y += h4.w * w.y; a3.z += h4.w * w.z; a3.w += h4.w * w.w;
        }
        #pragma unroll
        for (int r = 0; r < 4; ++r) {
            int row = row0 + rg * 4 + r;
            float dv = g_dinv[row];
            float4 a = (r == 0) ? a0 : (r == 1) ? a1 : (r == 2) ? a2 : a3;
            float4 o;
            o.x = dv * a.x; o.y = dv * a.y; o.z = dv * a.z; o.w = dv * a.w;
            *(float4*)&outp[(size_t)row * HID + cg * 4] = o;
        }
    }
}

// ---------------- graph boundaries (batch is sorted) ----------------
__global__ void k_bounds(const void* batch) {
    int i = threadIdx.x;
    if (i > N_GRAPH) return;
    int lo = 0, hi = N_NODES;
    while (lo < hi) {
        int mid = (lo + hi) >> 1;
        if (load_idx(batch, mid) < i) lo = mid + 1; else hi = mid;
    }
    g_gb[i] = lo;
}

// ---------------- pool: partial sums (8 splits per graph) then divide ----------------
__global__ void k_pool(const float* __restrict__ h, float* __restrict__ outp) {
    int g = blockIdx.x >> 3, part = blockIdx.x & 7;
    int c = threadIdx.x;
    int s = g_gb[g], e = g_gb[g + 1];
    float acc = 0.0f;
    for (int r = s + part; r < e; r += 8) acc += h[(size_t)r * HID + c];
    atomicAdd(&outp[g * HID + c], acc);
}

__global__ void k_div(float* outp) {
    int i = blockIdx.x * blockDim.x + threadIdx.x;
    if (i >= N_GRAPH * HID) return;
    int g = i >> 7;
    float cnt = (float)(g_gb[g + 1] - g_gb[g]);
    outp[i] /= fmaxf(cnt, 1.0f);
}

// ---------------- launch ----------------
extern "C" void kernel_launch(void* const* d_in, const int* in_sizes, int n_in,
                              void* d_out, int out_size) {
    const float* x  = (const float*)d_in[0];
    const void*  ei = d_in[1];
    const void*  batch = d_in[2];
    const float* W1 = (const float*)d_in[3];
    const float* b1 = (const float*)d_in[4];
    const float* W2 = (const float*)d_in[5];
    const float* b2 = (const float*)d_in[6];
    float* out = (float*)d_out;

    void* degp; cudaGetSymbolAddress(&degp, g_deg);
    void* curp; cudaGetSymbolAddress(&curp, g_cur);
    void* bufA; cudaGetSymbolAddress(&bufA, g_bufA);
    void* bufB; cudaGetSymbolAddress(&bufB, g_bufB);

    static int smem_set = 0;
    const int h2w2_smem = (HID * HID + HID * HT_PITCH) * sizeof(float);  // 83968
    if (!smem_set) {
        cudaFuncSetAttribute(k_h2w2, cudaFuncAttributeMaxDynamicSharedMemorySize, h2w2_smem);
        smem_set = 1;
    }

    k_detect<<<1, 1>>>((const int*)ei);
    cudaMemsetAsync(degp, 0, N_NODES * sizeof(int));
    cudaMemsetAsync(curp, 0, N_NODES * sizeof(int));

    const int EB = (N_EDGES + 255) / 256;
    k_deg<<<EB, 256>>>(ei);
    k_dinv<<<(N_NODES + 255) / 256, 256>>>();
    k_scan1<<<SCAN_BLKS, SCAN_CHUNK>>>();
    k_scan2<<<1, 256>>>();
    k_scan3<<<SCAN_BLKS, SCAN_CHUNK>>>();
    k_fill<<<EB, 256>>>(ei);

    k_xw1<<<N_NODES, HID>>>(x, W1);                               // -> bufA (g0)
    k_gather<<<(N_NODES * 32 + 255) / 256, 256>>>((float*)bufA, b1, (float*)bufB);  // -> h2
    k_h2w2<<<296, 256, h2w2_smem>>>((float*)bufB, W2, (float*)bufA);                // -> g2
    k_gather<<<(N_NODES * 32 + 255) / 256, 256>>>((float*)bufA, b2, (float*)bufB);  // -> h3

    k_bounds<<<1, 128>>>(batch);
    cudaMemsetAsync(out, 0, N_GRAPH * HID * sizeof(float));
    k_pool<<<N_GRAPH * 8, HID>>>((float*)bufB, out);
    k_div<<<(N_GRAPH * HID + 127) / 128, 128>>>(out);
}

// round 2
// speedup vs baseline: 1.1461x; 1.1461x over previous
#include <cuda_runtime.h>
#include <cuda_fp16.h>
#include <stdint.h>

#define N_NODES 100000
#define N_EDGES 1600000
#define N_GRAPH 64
#define HID 128
#define IN_C 4
#define SCAN_CHUNK 512
#define SCAN_BLKS ((N_NODES + SCAN_CHUNK - 1) / SCAN_CHUNK)   // 196

// ---------------- scratch (static device allocations) ----------------
__device__ float  g_f32[(size_t)N_NODES * HID];    // 51.2 MB  (h2, then h3)
__device__ __half g_h16A[(size_t)N_NODES * HID];   // 25.6 MB  (g0)
__device__ __half g_h16B[(size_t)N_NODES * HID];   // 25.6 MB  (g2)
__device__ int   g_csr[N_EDGES];
__device__ int   g_deg[N_NODES];
__device__ int   g_off[N_NODES + 1];
__device__ int   g_cur[N_NODES];
__device__ float g_dinv[N_NODES];
__device__ int   g_bsum[SCAN_BLKS];
__device__ int   g_gb[N_GRAPH + 1];
__device__ int   g_is64;

// ---------------- dtype detection ----------------
__global__ void k_detect(const int* ei32) {
    int all0 = 1;
    for (int k = 1; k < 129; k += 2) all0 &= (ei32[k] == 0);
    g_is64 = all0;
}

__device__ __forceinline__ int load_idx(const void* p, long long i) {
    if (g_is64) return (int)((const long long*)p)[i];
    return ((const int*)p)[i];
}

// ---------------- degree count ----------------
__global__ void k_deg(const void* ei) {
    int e = blockIdx.x * blockDim.x + threadIdx.x;
    if (e >= N_EDGES) return;
    int d = load_idx(ei, (long long)N_EDGES + e);
    atomicAdd(&g_deg[d], 1);
}

__global__ void k_dinv() {
    int v = blockIdx.x * blockDim.x + threadIdx.x;
    if (v >= N_NODES) return;
    g_dinv[v] = rsqrtf((float)(g_deg[v] + 1));   // +1 for self loop
}

// ---------------- exclusive scan of degrees -> CSR offsets ----------------
__global__ void k_scan1() {
    __shared__ int s[SCAN_CHUNK];
    int tid = threadIdx.x;
    int i = blockIdx.x * SCAN_CHUNK + tid;
    s[tid] = (i < N_NODES) ? g_deg[i] : 0;
    __syncthreads();
    for (int d = SCAN_CHUNK / 2; d > 0; d >>= 1) {
        if (tid < d) s[tid] += s[tid + d];
        __syncthreads();
    }
    if (tid == 0) g_bsum[blockIdx.x] = s[0];
}

__global__ void k_scan2() {
    __shared__ int s[256];
    int tid = threadIdx.x;
    int v = (tid < SCAN_BLKS) ? g_bsum[tid] : 0;
    s[tid] = v;
    __syncthreads();
    for (int d = 1; d < 256; d <<= 1) {
        int t = (tid >= d) ? s[tid - d] : 0;
        __syncthreads();
        s[tid] += t;
        __syncthreads();
    }
    if (tid < SCAN_BLKS) g_bsum[tid] = s[tid] - v;   // exclusive
}

__global__ void k_scan3() {
    __shared__ int s[SCAN_CHUNK];
    int tid = threadIdx.x;
    int i = blockIdx.x * SCAN_CHUNK + tid;
    int v = (i < N_NODES) ? g_deg[i] : 0;
    s[tid] = v;
    __syncthreads();
    for (int d = 1; d < SCAN_CHUNK; d <<= 1) {
        int t = (tid >= d) ? s[tid - d] : 0;
        __syncthreads();
        s[tid] += t;
        __syncthreads();
    }
    if (i < N_NODES) g_off[i] = g_bsum[blockIdx.x] + s[tid] - v;
    if (i == 0) g_off[N_NODES] = N_EDGES;
}

// ---------------- CSR fill (counting sort by dst) ----------------
__global__ void k_fill(const void* ei) {
    int e = blockIdx.x * blockDim.x + threadIdx.x;
    if (e >= N_EDGES) return;
    int s = load_idx(ei, e);
    int d = load_idx(ei, (long long)N_EDGES + e);
    int pos = g_off[d] + atomicAdd(&g_cur[d], 1);
    g_csr[pos] = s;
}

// ---------------- layer-1 input transform: g0 = fp16( dinv * (x @ W1) ) ----------------
__global__ void k_xw1(const float* __restrict__ x, const float* __restrict__ W1,
                      __half* __restrict__ outh) {
    __shared__ float xs[IN_C];
    int v = blockIdx.x;
    int c = threadIdx.x;
    if (c < IN_C) xs[c] = x[v * IN_C + c];
    __syncthreads();
    float acc = xs[0] * W1[c] + xs[1] * W1[HID + c]
              + xs[2] * W1[2 * HID + c] + xs[3] * W1[3 * HID + c];
    outh[(size_t)v * HID + c] = __float2half(g_dinv[v] * acc);
}

// ---------------- fp16 gather ----------------
// out[v] = relu( dinv[v] * (sum_{src in(v)} g[src] + g[v]) + b ),  fp32 accumulate/output.
__device__ __forceinline__ float4 h4f(uint2 u) {
    float2 a = __half22float2(*(const __half2*)&u.x);
    float2 b = __half22float2(*(const __half2*)&u.y);
    return make_float4(a.x, a.y, b.x, b.y);
}

__global__ void k_gather(const __half* __restrict__ gin, const float* __restrict__ bias,
                         float* __restrict__ gout) {
    int warp = (blockIdx.x * blockDim.x + threadIdx.x) >> 5;
    int lane = threadIdx.x & 31;
    if (warp >= N_NODES) return;
    int v = warp;
    const uint2* gin2 = (const uint2*)gin;
    float4 acc = h4f(gin2[(size_t)v * 32 + lane]);   // self loop
    int j = g_off[v], e = g_off[v + 1];
    for (; j + 3 < e; j += 4) {
        int i0 = __ldg(&g_csr[j]);
        int i1 = __ldg(&g_csr[j + 1]);
        int i2 = __ldg(&g_csr[j + 2]);
        int i3 = __ldg(&g_csr[j + 3]);
        float4 t0 = h4f(__ldg(&gin2[(size_t)i0 * 32 + lane]));
        float4 t1 = h4f(__ldg(&gin2[(size_t)i1 * 32 + lane]));
        float4 t2 = h4f(__ldg(&gin2[(size_t)i2 * 32 + lane]));
        float4 t3 = h4f(__ldg(&gin2[(size_t)i3 * 32 + lane]));
        acc.x += t0.x + t1.x + t2.x + t3.x;
        acc.y += t0.y + t1.y + t2.y + t3.y;
        acc.z += t0.z + t1.z + t2.z + t3.z;
        acc.w += t0.w + t1.w + t2.w + t3.w;
    }
    for (; j < e; ++j) {
        int i0 = __ldg(&g_csr[j]);
        float4 t0 = h4f(__ldg(&gin2[(size_t)i0 * 32 + lane]));
        acc.x += t0.x; acc.y += t0.y; acc.z += t0.z; acc.w += t0.w;
    }
    float dv = g_dinv[v];
    float4 bb = ((const float4*)bias)[lane];
    float4 r;
    r.x = fmaxf(dv * acc.x + bb.x, 0.0f);
    r.y = fmaxf(dv * acc.y + bb.y, 0.0f);
    r.z = fmaxf(dv * acc.z + bb.z, 0.0f);
    r.w = fmaxf(dv * acc.w + bb.w, 0.0f);
    ((float4*)gout)[(size_t)v * 32 + lane] = r;
}

// ---------------- dense transform: g2 = fp16( dinv * (hin @ W2) )  (128x128) ----------------
#define HT_PITCH 36
__global__ void k_h2w2(const float* __restrict__ hin, const float* __restrict__ W2,
                       __half* __restrict__ outh) {
    extern __shared__ float sm[];
    float* W2s = sm;                       // 128*128
    float* hsT = sm + HID * HID;           // [128][HT_PITCH]
    int t = threadIdx.x;
    for (int i = t; i < HID * HID; i += 256) W2s[i] = W2[i];
    int cg = t & 31;   // cols cg*4 .. cg*4+3
    int rg = t >> 5;   // rows rg*4 .. rg*4+3
    const int ntiles = N_NODES / 32;       // 3125
    for (int tile = blockIdx.x; tile < ntiles; tile += gridDim.x) {
        int row0 = tile * 32;
        __syncthreads();                   // also covers initial W2 load
        for (int i = t; i < 32 * HID; i += 256) {
            int r = i >> 7, c = i & 127;
            hsT[c * HT_PITCH + r] = hin[(size_t)(row0 + r) * HID + c];
        }
        __syncthreads();
        float4 a0 = {0,0,0,0}, a1 = {0,0,0,0}, a2 = {0,0,0,0}, a3 = {0,0,0,0};
        #pragma unroll 4
        for (int k = 0; k < HID; ++k) {
            float4 h4 = *(const float4*)&hsT[k * HT_PITCH + rg * 4];
            float4 w  = *(const float4*)&W2s[k * HID + cg * 4];
            a0.x += h4.x * w.x; a0.y += h4.x * w.y; a0.z += h4.x * w.z; a0.w += h4.x * w.w;
            a1.x += h4.y * w.x; a1.y += h4.y * w.y; a1.z += h4.y * w.z; a1.w += h4.y * w.w;
            a2.x += h4.z * w.x; a2.y += h4.z * w.y; a2.z += h4.z * w.z; a2.w += h4.z * w.w;
            a3.x += h4.w * w.x; a3.y += h4.w * w.y; a3.z += h4.w * w.z; a3.w += h4.w * w.w;
        }
        #pragma unroll
        for (int r = 0; r < 4; ++r) {
            int row = row0 + rg * 4 + r;
            float dv = g_dinv[row];
            float4 a = (r == 0) ? a0 : (r == 1) ? a1 : (r == 2) ? a2 : a3;
            __half2 p0 = __floats2half2_rn(dv * a.x, dv * a.y);
            __half2 p1 = __floats2half2_rn(dv * a.z, dv * a.w);
            uint2 u;
            u.x = *(const unsigned*)&p0;
            u.y = *(const unsigned*)&p1;
            ((uint2*)(outh + (size_t)row * HID))[cg] = u;
        }
    }
}

// ---------------- graph boundaries (batch is sorted) ----------------
__global__ void k_bounds(const void* batch) {
    int i = threadIdx.x;
    if (i > N_GRAPH) return;
    int lo = 0, hi = N_NODES;
    while (lo < hi) {
        int mid = (lo + hi) >> 1;
        if (load_idx(batch, mid) < i) lo = mid + 1; else hi = mid;
    }
    g_gb[i] = lo;
}

// ---------------- pool: partial sums (8 splits per graph) then divide ----------------
__global__ void k_pool(const float* __restrict__ h, float* __restrict__ outp) {
    int g = blockIdx.x >> 3, part = blockIdx.x & 7;
    int c = threadIdx.x;
    int s = g_gb[g], e = g_gb[g + 1];
    float acc = 0.0f;
    for (int r = s + part; r < e; r += 8) acc += h[(size_t)r * HID + c];
    atomicAdd(&outp[g * HID + c], acc);
}

__global__ void k_div(float* outp) {
    int i = blockIdx.x * blockDim.x + threadIdx.x;
    if (i >= N_GRAPH * HID) return;
    int g = i >> 7;
    float cnt = (float)(g_gb[g + 1] - g_gb[g]);
    outp[i] /= fmaxf(cnt, 1.0f);
}

// ---------------- launch ----------------
extern "C" void kernel_launch(void* const* d_in, const int* in_sizes, int n_in,
                              void* d_out, int out_size) {
    const float* x  = (const float*)d_in[0];
    const void*  ei = d_in[1];
    const void*  batch = d_in[2];
    const float* W1 = (const float*)d_in[3];
    const float* b1 = (const float*)d_in[4];
    const float* W2 = (const float*)d_in[5];
    const float* b2 = (const float*)d_in[6];
    float* out = (float*)d_out;

    void* degp;  cudaGetSymbolAddress(&degp, g_deg);
    void* curp;  cudaGetSymbolAddress(&curp, g_cur);
    void* f32p;  cudaGetSymbolAddress(&f32p, g_f32);
    void* h16Ap; cudaGetSymbolAddress(&h16Ap, g_h16A);
    void* h16Bp; cudaGetSymbolAddress(&h16Bp, g_h16B);

    static int smem_set = 0;
    const int h2w2_smem = (HID * HID + HID * HT_PITCH) * sizeof(float);  // 83968
    if (!smem_set) {
        cudaFuncSetAttribute(k_h2w2, cudaFuncAttributeMaxDynamicSharedMemorySize, h2w2_smem);
        smem_set = 1;
    }

    k_detect<<<1, 1>>>((const int*)ei);
    cudaMemsetAsync(degp, 0, N_NODES * sizeof(int));
    cudaMemsetAsync(curp, 0, N_NODES * sizeof(int));

    const int EB = (N_EDGES + 255) / 256;
    k_deg<<<EB, 256>>>(ei);
    k_dinv<<<(N_NODES + 255) / 256, 256>>>();
    k_scan1<<<SCAN_BLKS, SCAN_CHUNK>>>();
    k_scan2<<<1, 256>>>();
    k_scan3<<<SCAN_BLKS, SCAN_CHUNK>>>();
    k_fill<<<EB, 256>>>(ei);

    k_xw1<<<N_NODES, HID>>>(x, W1, (__half*)h16Ap);                                  // g0 (fp16)
    k_gather<<<(N_NODES * 32 + 255) / 256, 256>>>((__half*)h16Ap, b1, (float*)f32p); // h2 (fp32)
    k_h2w2<<<296, 256, h2w2_smem>>>((float*)f32p, W2, (__half*)h16Bp);               // g2 (fp16)
    k_gather<<<(N_NODES * 32 + 255) / 256, 256>>>((__half*)h16Bp, b2, (float*)f32p); // h3 (fp32)

    k_bounds<<<1, 128>>>(batch);
    cudaMemsetAsync(out, 0, N_GRAPH * HID * sizeof(float));
    k_pool<<<N_GRAPH * 8, HID>>>((float*)f32p, out);
    k_div<<<(N_GRAPH * HID + 127) / 128, 128>>>(out);
}

// round 3
// speedup vs baseline: 1.5705x; 1.3703x over previous
#include <cuda_runtime.h>
#include <cuda_fp16.h>
#include <mma.h>
#include <stdint.h>
using namespace nvcuda;

#define N_NODES 100000
#define N_EDGES 1600000
#define N_GRAPH 64
#define HID 128
#define IN_C 4
#define SCAN_CHUNK 512
#define SCAN_BLKS ((N_NODES + SCAN_CHUNK - 1) / SCAN_CHUNK)   // 196
#define N_PAD ((N_NODES + 127) & ~127)                        // 100096 (GEMM tail)

// ---------------- scratch (static device allocations) ----------------
__device__ float  g_f32[(size_t)N_NODES * HID];     // h3 (fp32, pooled)
__device__ __half g_h16A[(size_t)N_PAD * HID];      // g0, then h2 (fp16)
__device__ __half g_h16B[(size_t)N_PAD * HID];      // g2 (fp16)
__device__ int   g_csr[N_EDGES];
__device__ int   g_deg[N_NODES];
__device__ int   g_off[N_NODES + 1];
__device__ int   g_cur[N_NODES];
__device__ float g_dinv[N_NODES];
__device__ int   g_bsum[SCAN_BLKS];
__device__ int   g_gb[N_GRAPH + 1];
__device__ int   g_is64;

// ---------------- dtype detection ----------------
__global__ void k_detect(const int* ei32) {
    int all0 = 1;
    for (int k = 1; k < 129; k += 2) all0 &= (ei32[k] == 0);
    g_is64 = all0;
}

__device__ __forceinline__ int load_idx(const void* p, long long i) {
    if (g_is64) return (int)((const long long*)p)[i];
    return ((const int*)p)[i];
}

// ---------------- degree count ----------------
__global__ void k_deg(const void* ei) {
    int e = blockIdx.x * blockDim.x + threadIdx.x;
    if (e >= N_EDGES) return;
    int d = load_idx(ei, (long long)N_EDGES + e);
    atomicAdd(&g_deg[d], 1);
}

__global__ void k_dinv() {
    int v = blockIdx.x * blockDim.x + threadIdx.x;
    if (v >= N_NODES) return;
    g_dinv[v] = rsqrtf((float)(g_deg[v] + 1));   // +1 for self loop
}

// ---------------- exclusive scan of degrees -> CSR offsets ----------------
__global__ void k_scan1() {
    __shared__ int s[SCAN_CHUNK];
    int tid = threadIdx.x;
    int i = blockIdx.x * SCAN_CHUNK + tid;
    s[tid] = (i < N_NODES) ? g_deg[i] : 0;
    __syncthreads();
    for (int d = SCAN_CHUNK / 2; d > 0; d >>= 1) {
        if (tid < d) s[tid] += s[tid + d];
        __syncthreads();
    }
    if (tid == 0) g_bsum[blockIdx.x] = s[0];
}

__global__ void k_scan2() {
    __shared__ int s[256];
    int tid = threadIdx.x;
    int v = (tid < SCAN_BLKS) ? g_bsum[tid] : 0;
    s[tid] = v;
    __syncthreads();
    for (int d = 1; d < 256; d <<= 1) {
        int t = (tid >= d) ? s[tid - d] : 0;
        __syncthreads();
        s[tid] += t;
        __syncthreads();
    }
    if (tid < SCAN_BLKS) g_bsum[tid] = s[tid] - v;   // exclusive
}

__global__ void k_scan3() {
    __shared__ int s[SCAN_CHUNK];
    int tid = threadIdx.x;
    int i = blockIdx.x * SCAN_CHUNK + tid;
    int v = (i < N_NODES) ? g_deg[i] : 0;
    s[tid] = v;
    __syncthreads();
    for (int d = 1; d < SCAN_CHUNK; d <<= 1) {
        int t = (tid >= d) ? s[tid - d] : 0;
        __syncthreads();
        s[tid] += t;
        __syncthreads();
    }
    if (i < N_NODES) g_off[i] = g_bsum[blockIdx.x] + s[tid] - v;
    if (i == 0) g_off[N_NODES] = N_EDGES;
}

// ---------------- CSR fill (counting sort by dst) ----------------
__global__ void k_fill(const void* ei) {
    int e = blockIdx.x * blockDim.x + threadIdx.x;
    if (e >= N_EDGES) return;
    int s = load_idx(ei, e);
    int d = load_idx(ei, (long long)N_EDGES + e);
    int pos = g_off[d] + atomicAdd(&g_cur[d], 1);
    g_csr[pos] = s;
}

// ---------------- layer-1 input transform: g0 = fp16( dinv * (x @ W1) ) ----------------
__global__ void k_xw1(const float* __restrict__ x, const float* __restrict__ W1,
                      __half* __restrict__ outh) {
    __shared__ float xs[IN_C];
    int v = blockIdx.x;
    int c = threadIdx.x;
    if (c < IN_C) xs[c] = x[v * IN_C + c];
    __syncthreads();
    float acc = xs[0] * W1[c] + xs[1] * W1[HID + c]
              + xs[2] * W1[2 * HID + c] + xs[3] * W1[3 * HID + c];
    outh[(size_t)v * HID + c] = __float2half(g_dinv[v] * acc);
}

// ---------------- fp16 gather ----------------
__device__ __forceinline__ float4 h4f(uint2 u) {
    float2 a = __half22float2(*(const __half2*)&u.x);
    float2 b = __half22float2(*(const __half2*)&u.y);
    return make_float4(a.x, a.y, b.x, b.y);
}

template <bool OUT16>
__global__ void k_gather(const __half* __restrict__ gin, const float* __restrict__ bias,
                         void* __restrict__ gout) {
    int warp = (blockIdx.x * blockDim.x + threadIdx.x) >> 5;
    int lane = threadIdx.x & 31;
    if (warp >= N_NODES) return;
    int v = warp;
    const uint2* gin2 = (const uint2*)gin;
    float4 acc = h4f(gin2[(size_t)v * 32 + lane]);   // self loop
    int j = g_off[v], e = g_off[v + 1];
    for (; j + 3 < e; j += 4) {
        int i0 = __ldg(&g_csr[j]);
        int i1 = __ldg(&g_csr[j + 1]);
        int i2 = __ldg(&g_csr[j + 2]);
        int i3 = __ldg(&g_csr[j + 3]);
        float4 t0 = h4f(__ldg(&gin2[(size_t)i0 * 32 + lane]));
        float4 t1 = h4f(__ldg(&gin2[(size_t)i1 * 32 + lane]));
        float4 t2 = h4f(__ldg(&gin2[(size_t)i2 * 32 + lane]));
        float4 t3 = h4f(__ldg(&gin2[(size_t)i3 * 32 + lane]));
        acc.x += t0.x + t1.x + t2.x + t3.x;
        acc.y += t0.y + t1.y + t2.y + t3.y;
        acc.z += t0.z + t1.z + t2.z + t3.z;
        acc.w += t0.w + t1.w + t2.w + t3.w;
    }
    for (; j < e; ++j) {
        int i0 = __ldg(&g_csr[j]);
        float4 t0 = h4f(__ldg(&gin2[(size_t)i0 * 32 + lane]));
        acc.x += t0.x; acc.y += t0.y; acc.z += t0.z; acc.w += t0.w;
    }
    float dv = g_dinv[v];
    float4 bb = ((const float4*)bias)[lane];
    float4 r;
    r.x = fmaxf(dv * acc.x + bb.x, 0.0f);
    r.y = fmaxf(dv * acc.y + bb.y, 0.0f);
    r.z = fmaxf(dv * acc.z + bb.z, 0.0f);
    r.w = fmaxf(dv * acc.w + bb.w, 0.0f);
    if (OUT16) {
        __half2 p0 = __floats2half2_rn(r.x, r.y);
        __half2 p1 = __floats2half2_rn(r.z, r.w);
        uint2 u;
        u.x = *(const unsigned*)&p0;
        u.y = *(const unsigned*)&p1;
        ((uint2*)gout)[(size_t)v * 32 + lane] = u;
    } else {
        ((float4*)gout)[(size_t)v * 32 + lane] = r;
    }
}

// ---------------- tensor-core GEMM: g2 = fp16( dinv * (h2 @ W2) ) ----------------
// Block: 256 thr = 8 warps. Block tile: 128 rows x 128 cols. Warp: 16 rows x 128 cols.
// A (h2, fp16) loaded straight from gmem (L2-resident); W2 converted to fp16 in smem.
#define MM_PITCH 136   // halves (B) / floats (staging) per row; 16B-multiple
__global__ void k_h2w2_mma(const __half* __restrict__ hin, const float* __restrict__ W2,
                           __half* __restrict__ outh) {
    extern __shared__ __half smh[];
    __half* W2h = smh;                                         // [128][MM_PITCH] fp16
    float* stage = (float*)(smh + HID * MM_PITCH);             // [8][16][MM_PITCH] fp32
    int t = threadIdx.x;
    int warp = t >> 5, lane = t & 31;
    for (int i = t; i < HID * HID; i += 256) {
        int r = i >> 7, c = i & 127;
        W2h[r * MM_PITCH + c] = __float2half(W2[i]);
    }
    __syncthreads();

    float* st = stage + warp * 16 * MM_PITCH;
    const int ntiles = N_PAD / 128;   // 782
    for (int tile = blockIdx.x; tile < ntiles; tile += gridDim.x) {
        int row0 = tile * 128 + warp * 16;
        wmma::fragment<wmma::accumulator, 16, 16, 16, float> c[8];
        #pragma unroll
        for (int n = 0; n < 8; ++n) wmma::fill_fragment(c[n], 0.0f);
        #pragma unroll
        for (int k0 = 0; k0 < HID; k0 += 16) {
            wmma::fragment<wmma::matrix_a, 16, 16, 16, __half, wmma::row_major> a;
            wmma::load_matrix_sync(a, hin + (size_t)row0 * HID + k0, HID);
            #pragma unroll
            for (int n = 0; n < 8; ++n) {
                wmma::fragment<wmma::matrix_b, 16, 16, 16, __half, wmma::row_major> b;
                wmma::load_matrix_sync(b, W2h + k0 * MM_PITCH + n * 16, MM_PITCH);
                wmma::mma_sync(c[n], a, b, c[n]);
            }
        }
        #pragma unroll
        for (int n = 0; n < 8; ++n)
            wmma::store_matrix_sync(st + n * 16, c[n], MM_PITCH, wmma::mem_row_major);
        __syncwarp();
        #pragma unroll
        for (int r = 0; r < 16; ++r) {
            int row = row0 + r;
            if (row < N_NODES) {
                float dv = g_dinv[row];
                float4 v = *(const float4*)&st[r * MM_PITCH + lane * 4];
                __half2 p0 = __floats2half2_rn(dv * v.x, dv * v.y);
                __half2 p1 = __floats2half2_rn(dv * v.z, dv * v.w);
                uint2 u;
                u.x = *(const unsigned*)&p0;
                u.y = *(const unsigned*)&p1;
                *(uint2*)&outh[(size_t)row * HID + lane * 4] = u;
            }
        }
        __syncwarp();
    }
}

// ---------------- graph boundaries (batch is sorted) ----------------
__global__ void k_bounds(const void* batch) {
    int i = threadIdx.x;
    if (i > N_GRAPH) return;
    int lo = 0, hi = N_NODES;
    while (lo < hi) {
        int mid = (lo + hi) >> 1;
        if (load_idx(batch, mid) < i) lo = mid + 1; else hi = mid;
    }
    g_gb[i] = lo;
}

// ---------------- pool: partial sums (8 splits per graph) then divide ----------------
__global__ void k_pool(const float* __restrict__ h, float* __restrict__ outp) {
    int g = blockIdx.x >> 3, part = blockIdx.x & 7;
    int c = threadIdx.x;
    int s = g_gb[g], e = g_gb[g + 1];
    float acc = 0.0f;
    for (int r = s + part; r < e; r += 8) acc += h[(size_t)r * HID + c];
    atomicAdd(&outp[g * HID + c], acc);
}

__global__ void k_div(float* outp) {
    int i = blockIdx.x * blockDim.x + threadIdx.x;
    if (i >= N_GRAPH * HID) return;
    int g = i >> 7;
    float cnt = (float)(g_gb[g + 1] - g_gb[g]);
    outp[i] /= fmaxf(cnt, 1.0f);
}

// ---------------- launch ----------------
extern "C" void kernel_launch(void* const* d_in, const int* in_sizes, int n_in,
                              void* d_out, int out_size) {
    const float* x  = (const float*)d_in[0];
    const void*  ei = d_in[1];
    const void*  batch = d_in[2];
    const float* W1 = (const float*)d_in[3];
    const float* b1 = (const float*)d_in[4];
    const float* W2 = (const float*)d_in[5];
    const float* b2 = (const float*)d_in[6];
    float* out = (float*)d_out;

    void* degp;  cudaGetSymbolAddress(&degp, g_deg);
    void* curp;  cudaGetSymbolAddress(&curp, g_cur);
    void* f32p;  cudaGetSymbolAddress(&f32p, g_f32);
    void* h16Ap; cudaGetSymbolAddress(&h16Ap, g_h16A);
    void* h16Bp; cudaGetSymbolAddress(&h16Bp, g_h16B);

    static int smem_set = 0;
    const int mma_smem = HID * MM_PITCH * sizeof(__half) + 8 * 16 * MM_PITCH * sizeof(float); // 104448
    if (!smem_set) {
        cudaFuncSetAttribute(k_h2w2_mma, cudaFuncAttributeMaxDynamicSharedMemorySize, mma_smem);
        smem_set = 1;
    }

    k_detect<<<1, 1>>>((const int*)ei);
    cudaMemsetAsync(degp, 0, N_NODES * sizeof(int));
    cudaMemsetAsync(curp, 0, N_NODES * sizeof(int));

    const int EB = (N_EDGES + 255) / 256;
    k_deg<<<EB, 256>>>(ei);
    k_dinv<<<(N_NODES + 255) / 256, 256>>>();
    k_scan1<<<SCAN_BLKS, SCAN_CHUNK>>>();
    k_scan2<<<1, 256>>>();
    k_scan3<<<SCAN_BLKS, SCAN_CHUNK>>>();
    k_fill<<<EB, 256>>>(ei);

    k_xw1<<<N_NODES, HID>>>(x, W1, (__half*)h16Ap);                                       // g0 (fp16)
    // h2 (fp16) goes back into g_h16A? No: gather reads g_h16A while writing — use B.
    k_gather<true><<<(N_NODES * 32 + 255) / 256, 256>>>((__half*)h16Ap, b1, h16Bp);       // h2 -> B
    k_h2w2_mma<<<296, 256, mma_smem>>>((__half*)h16Bp, W2, (__half*)h16Ap);               // g2 -> A
    k_gather<false><<<(N_NODES * 32 + 255) / 256, 256>>>((__half*)h16Ap, b2, f32p);       // h3 (fp32)

    k_bounds<<<1, 128>>>(batch);
    cudaMemsetAsync(out, 0, N_GRAPH * HID * sizeof(float));
    k_pool<<<N_GRAPH * 8, HID>>>((float*)f32p, out);
    k_div<<<(N_GRAPH * HID + 127) / 128, 128>>>(out);
}

// round 4
// speedup vs baseline: 1.9817x; 1.2618x over previous
#include <cuda_runtime.h>
#include <cuda_fp16.h>
#include <mma.h>
#include <stdint.h>
using namespace nvcuda;

#define N_NODES 100000
#define N_EDGES 1600000
#define N_GRAPH 64
#define HID 128
#define IN_C 4
#define SCAN_CHUNK 512
#define SCAN_BLKS ((N_NODES + SCAN_CHUNK - 1) / SCAN_CHUNK)   // 196
#define N_PAD ((N_NODES + 127) & ~127)                        // 100096

// ---------------- scratch ----------------
__device__ __half g_h16A[(size_t)N_PAD * HID];      // g0 -> g2
__device__ __half g_h16B[(size_t)N_PAD * HID];      // h2 -> h3
__device__ int   g_csr[N_EDGES];
__device__ int   g_deg[N_NODES + 1];                // [N_NODES] = scan cursor
__device__ int   g_off[N_NODES];                    // start (pre-fill) -> end (post-fill)
__device__ float g_dinv[N_NODES];
__device__ int   g_is64;

// ---------------- dtype detection ----------------
__global__ void k_detect(const int* ei32) {
    // int64 values < 2^31: odd 32-bit words are all zero. For int32 data these
    // words are actual node ids (P(zero) ~ 1e-5 each) -> 64-way AND is decisive.
    int t = threadIdx.x;
    int z = (ei32[2 * t + 1] == 0);
    unsigned m = __ballot_sync(0xFFFFFFFFu, z);
    __shared__ int ok[2];
    if ((t & 31) == 0) ok[t >> 5] = (m == 0xFFFFFFFFu);
    __syncthreads();
    if (t == 0) g_is64 = ok[0] & ok[1];
}

__device__ __forceinline__ int load_idx(const void* p, long long i) {
    if (g_is64) return (int)((const long long*)p)[i];
    return ((const int*)p)[i];
}

// ---------------- degree count ----------------
__global__ void k_deg(const void* ei) {
    int e = blockIdx.x * blockDim.x + threadIdx.x;
    if (e >= N_EDGES) return;
    int d = load_idx(ei, (long long)N_EDGES + e);
    atomicAdd(&g_deg[d], 1);
}

// ---------------- fused scan: g_off[v]=segment start, g_dinv ----------------
__global__ void k_scan() {
    int tid = threadIdx.x;
    int i = blockIdx.x * SCAN_CHUNK + tid;
    int lane = tid & 31, wid = tid >> 5;          // 16 warps
    int d = (i < N_NODES) ? g_deg[i] : 0;
    int v = d;
    #pragma unroll
    for (int o = 1; o < 32; o <<= 1) {
        int t = __shfl_up_sync(0xFFFFFFFFu, v, o);
        if (lane >= o) v += t;
    }
    __shared__ int ws[16];
    __shared__ int base;
    if (lane == 31) ws[wid] = v;
    __syncthreads();
    if (wid == 0) {
        int s = (lane < 16) ? ws[lane] : 0;
        int sv = s;
        #pragma unroll
        for (int o = 1; o < 16; o <<= 1) {
            int t = __shfl_up_sync(0xFFFFFFFFu, sv, o);
            if (lane >= o) sv += t;
        }
        if (lane < 16) ws[lane] = sv - s;          // exclusive warp offsets
        if (lane == 15) base = atomicAdd(&g_deg[N_NODES], sv);  // sv = block total
    }
    __syncthreads();
    if (i < N_NODES) {
        g_off[i] = base + ws[wid] + (v - d);       // exclusive within block + base
        g_dinv[i] = rsqrtf((float)(d + 1));        // +1 self loop
    }
}

// ---------------- CSR fill: mutates g_off start -> end ----------------
__global__ void k_fill(const void* ei) {
    int e = blockIdx.x * blockDim.x + threadIdx.x;
    if (e >= N_EDGES) return;
    int s = load_idx(ei, e);
    int d = load_idx(ei, (long long)N_EDGES + e);
    int pos = atomicAdd(&g_off[d], 1);
    g_csr[pos] = s;
}

// ---------------- layer-1: g0 = fp16( dinv * (x @ W1) ), warp/node ----------------
__global__ void k_xw1(const float* __restrict__ x, const float* __restrict__ W1,
                      __half* __restrict__ outh) {
    int warp = (blockIdx.x * blockDim.x + threadIdx.x) >> 5;
    int lane = threadIdx.x & 31;
    int nwarps = (gridDim.x * blockDim.x) >> 5;
    const float4* W4 = (const float4*)W1;
    float4 w0 = __ldg(&W4[0 * 32 + lane]);
    float4 w1 = __ldg(&W4[1 * 32 + lane]);
    float4 w2 = __ldg(&W4[2 * 32 + lane]);
    float4 w3 = __ldg(&W4[3 * 32 + lane]);
    for (int vtx = warp; vtx < N_NODES; vtx += nwarps) {
        float xv = (lane < IN_C) ? __ldg(&x[vtx * IN_C + lane]) : 0.0f;
        float x0 = __shfl_sync(0xFFFFFFFFu, xv, 0);
        float x1 = __shfl_sync(0xFFFFFFFFu, xv, 1);
        float x2 = __shfl_sync(0xFFFFFFFFu, xv, 2);
        float x3 = __shfl_sync(0xFFFFFFFFu, xv, 3);
        float dv = g_dinv[vtx];
        float ax = dv * (x0 * w0.x + x1 * w1.x + x2 * w2.x + x3 * w3.x);
        float ay = dv * (x0 * w0.y + x1 * w1.y + x2 * w2.y + x3 * w3.y);
        float az = dv * (x0 * w0.z + x1 * w1.z + x2 * w2.z + x3 * w3.z);
        float aw = dv * (x0 * w0.w + x1 * w1.w + x2 * w2.w + x3 * w3.w);
        __half2 p0 = __floats2half2_rn(ax, ay);
        __half2 p1 = __floats2half2_rn(az, aw);
        uint2 u;
        u.x = *(const unsigned*)&p0;
        u.y = *(const unsigned*)&p1;
        ((uint2*)(outh + (size_t)vtx * HID))[lane] = u;
    }
}

// ---------------- fp16 gather, fp32 accumulate, fp16 out ----------------
__device__ __forceinline__ float4 h4f(uint2 u) {
    float2 a = __half22float2(*(const __half2*)&u.x);
    float2 b = __half22float2(*(const __half2*)&u.y);
    return make_float4(a.x, a.y, b.x, b.y);
}

__global__ void k_gather(const __half* __restrict__ gin, const float* __restrict__ bias,
                         __half* __restrict__ gout) {
    int warp = (blockIdx.x * blockDim.x + threadIdx.x) >> 5;
    int lane = threadIdx.x & 31;
    if (warp >= N_NODES) return;
    int v = warp;
    const uint2* gin2 = (const uint2*)gin;
    float4 acc = h4f(gin2[(size_t)v * 32 + lane]);   // self loop
    int e = g_off[v];                                // end (post-fill)
    int j = e - g_deg[v];                            // start
    for (; j + 3 < e; j += 4) {
        int i0 = __ldg(&g_csr[j]);
        int i1 = __ldg(&g_csr[j + 1]);
        int i2 = __ldg(&g_csr[j + 2]);
        int i3 = __ldg(&g_csr[j + 3]);
        float4 t0 = h4f(__ldg(&gin2[(size_t)i0 * 32 + lane]));
        float4 t1 = h4f(__ldg(&gin2[(size_t)i1 * 32 + lane]));
        float4 t2 = h4f(__ldg(&gin2[(size_t)i2 * 32 + lane]));
        float4 t3 = h4f(__ldg(&gin2[(size_t)i3 * 32 + lane]));
        acc.x += t0.x + t1.x + t2.x + t3.x;
        acc.y += t0.y + t1.y + t2.y + t3.y;
        acc.z += t0.z + t1.z + t2.z + t3.z;
        acc.w += t0.w + t1.w + t2.w + t3.w;
    }
    for (; j < e; ++j) {
        int i0 = __ldg(&g_csr[j]);
        float4 t0 = h4f(__ldg(&gin2[(size_t)i0 * 32 + lane]));
        acc.x += t0.x; acc.y += t0.y; acc.z += t0.z; acc.w += t0.w;
    }
    float dv = g_dinv[v];
    float4 bb = ((const float4*)bias)[lane];
    __half2 p0 = __floats2half2_rn(fmaxf(dv * acc.x + bb.x, 0.0f),
                                   fmaxf(dv * acc.y + bb.y, 0.0f));
    __half2 p1 = __floats2half2_rn(fmaxf(dv * acc.z + bb.z, 0.0f),
                                   fmaxf(dv * acc.w + bb.w, 0.0f));
    uint2 u;
    u.x = *(const unsigned*)&p0;
    u.y = *(const unsigned*)&p1;
    ((uint2*)gout)[(size_t)v * 32 + lane] = u;
}

// ---------------- tensor-core GEMM: g2 = fp16( dinv * (h2 @ W2) ) ----------------
#define MM_PITCH 136
__global__ void k_h2w2_mma(const __half* __restrict__ hin, const float* __restrict__ W2,
                           __half* __restrict__ outh) {
    extern __shared__ __half smh[];
    __half* W2h = smh;                                   // [128][MM_PITCH] fp16
    float* stage = (float*)(smh + HID * MM_PITCH);       // [8][16][MM_PITCH] fp32
    int t = threadIdx.x;
    int warp = t >> 5, lane = t & 31;
    for (int i = t; i < HID * HID; i += 256) {
        int r = i >> 7, c = i & 127;
        W2h[r * MM_PITCH + c] = __float2half(W2[i]);
    }
    __syncthreads();

    float* st = stage + warp * 16 * MM_PITCH;
    const int ntiles = N_PAD / 128;   // 782
    for (int tile = blockIdx.x; tile < ntiles; tile += gridDim.x) {
        int row0 = tile * 128 + warp * 16;
        wmma::fragment<wmma::accumulator, 16, 16, 16, float> c[8];
        #pragma unroll
        for (int n = 0; n < 8; ++n) wmma::fill_fragment(c[n], 0.0f);
        #pragma unroll
        for (int k0 = 0; k0 < HID; k0 += 16) {
            wmma::fragment<wmma::matrix_a, 16, 16, 16, __half, wmma::row_major> a;
            wmma::load_matrix_sync(a, hin + (size_t)row0 * HID + k0, HID);
            #pragma unroll
            for (int n = 0; n < 8; ++n) {
                wmma::fragment<wmma::matrix_b, 16, 16, 16, __half, wmma::row_major> b;
                wmma::load_matrix_sync(b, W2h + k0 * MM_PITCH + n * 16, MM_PITCH);
                wmma::mma_sync(c[n], a, b, c[n]);
            }
        }
        #pragma unroll
        for (int n = 0; n < 8; ++n)
            wmma::store_matrix_sync(st + n * 16, c[n], MM_PITCH, wmma::mem_row_major);
        __syncwarp();
        #pragma unroll
        for (int r = 0; r < 16; ++r) {
            int row = row0 + r;
            if (row < N_NODES) {
                float dv = g_dinv[row];
                float4 v = *(const float4*)&st[r * MM_PITCH + lane * 4];
                __half2 p0 = __floats2half2_rn(dv * v.x, dv * v.y);
                __half2 p1 = __floats2half2_rn(dv * v.z, dv * v.w);
                uint2 u;
                u.x = *(const unsigned*)&p0;
                u.y = *(const unsigned*)&p1;
                *(uint2*)&outh[(size_t)row * HID + lane * 4] = u;
            }
        }
        __syncwarp();
    }
}

// ---------------- fused pool: bounds + mean, one block per graph ----------------
__global__ void k_poolmean(const __half* __restrict__ h, const void* batch,
                           float* __restrict__ outp) {
    int g = blockIdx.x;
    __shared__ int sb[2];
    if (threadIdx.x < 2) {
        int target = g + threadIdx.x;
        int lo = 0, hi = N_NODES;
        while (lo < hi) {
            int mid = (lo + hi) >> 1;
            if (load_idx(batch, mid) < target) lo = mid + 1; else hi = mid;
        }
        sb[threadIdx.x] = lo;
    }
    __syncthreads();
    int s = sb[0], e = sb[1];
    int stream = threadIdx.x >> 6;     // 16 row streams
    int c2 = threadIdx.x & 63;         // half2 column
    const __half2* h2p = (const __half2*)h;
    float2 acc = make_float2(0.0f, 0.0f);
    #pragma unroll 4
    for (int r = s + stream; r < e; r += 16) {
        float2 t = __half22float2(h2p[(size_t)r * 64 + c2]);
        acc.x += t.x; acc.y += t.y;
    }
    __shared__ float2 red[1024];
    red[threadIdx.x] = acc;
    __syncthreads();
    if (threadIdx.x < 64) {
        float2 a = make_float2(0.0f, 0.0f);
        #pragma unroll
        for (int k = 0; k < 16; ++k) {
            float2 t = red[k * 64 + threadIdx.x];
            a.x += t.x; a.y += t.y;
        }
        float inv = 1.0f / fmaxf((float)(e - s), 1.0f);
        outp[g * HID + c2 * 2]     = a.x * inv;
        outp[g * HID + c2 * 2 + 1] = a.y * inv;
    }
}

// ---------------- launch ----------------
extern "C" void kernel_launch(void* const* d_in, const int* in_sizes, int n_in,
                              void* d_out, int out_size) {
    const float* x  = (const float*)d_in[0];
    const void*  ei = d_in[1];
    const void*  batch = d_in[2];
    const float* W1 = (const float*)d_in[3];
    const float* b1 = (const float*)d_in[4];
    const float* W2 = (const float*)d_in[5];
    const float* b2 = (const float*)d_in[6];
    float* out = (float*)d_out;

    void* degp;  cudaGetSymbolAddress(&degp, g_deg);
    void* h16Ap; cudaGetSymbolAddress(&h16Ap, g_h16A);
    void* h16Bp; cudaGetSymbolAddress(&h16Bp, g_h16B);

    static int smem_set = 0;
    const int mma_smem = HID * MM_PITCH * sizeof(__half) + 8 * 16 * MM_PITCH * sizeof(float);
    if (!smem_set) {
        cudaFuncSetAttribute(k_h2w2_mma, cudaFuncAttributeMaxDynamicSharedMemorySize, mma_smem);
        smem_set = 1;
    }

    k_detect<<<1, 64>>>((const int*)ei);
    cudaMemsetAsync(degp, 0, (N_NODES + 1) * sizeof(int));   // deg + scan cursor

    const int EB = (N_EDGES + 255) / 256;
    k_deg<<<EB, 256>>>(ei);
    k_scan<<<SCAN_BLKS, SCAN_CHUNK>>>();
    k_fill<<<EB, 256>>>(ei);

    k_xw1<<<256, 256>>>(x, W1, (__half*)h16Ap);                                   // g0 -> A
    k_gather<<<(N_NODES * 32 + 255) / 256, 256>>>((__half*)h16Ap, b1, (__half*)h16Bp); // h2 -> B
    k_h2w2_mma<<<296, 256, mma_smem>>>((__half*)h16Bp, W2, (__half*)h16Ap);       // g2 -> A
    k_gather<<<(N_NODES * 32 + 255) / 256, 256>>>((__half*)h16Ap, b2, (__half*)h16Bp); // h3 -> B

    k_poolmean<<<N_GRAPH, 1024>>>((__half*)h16Bp, batch, out);
}

// round 5
// speedup vs baseline: 2.0464x; 1.0327x over previous
#include <cuda_runtime.h>
#include <cuda_fp16.h>
#include <mma.h>
#include <stdint.h>
using namespace nvcuda;

#define N_NODES 100000
#define N_EDGES 1600000
#define N_GRAPH 64
#define HID 128
#define IN_C 4
#define SCAN_CHUNK 512
#define SCAN_BLKS ((N_NODES + SCAN_CHUNK - 1) / SCAN_CHUNK)   // 196
#define N_PAD ((N_NODES + 127) & ~127)                        // 100096

// ---------------- scratch ----------------
__device__ __half g_h16A[(size_t)N_PAD * HID];      // g0 -> g2
__device__ __half g_h16B[(size_t)N_PAD * HID];      // h2 -> h3
__device__ int   g_csr[N_EDGES];
__device__ int   g_deg[N_NODES + 1];                // [N_NODES] = scan cursor
__device__ int   g_off[N_NODES];                    // start (pre-fill) -> end (post-fill)
__device__ float g_dinv[N_NODES];
__device__ int   g_is64;

// ---------------- dtype detection ----------------
__global__ void k_detect(const int* ei32) {
    int t = threadIdx.x;
    int z = (ei32[2 * t + 1] == 0);
    unsigned m = __ballot_sync(0xFFFFFFFFu, z);
    __shared__ int ok[2];
    if ((t & 31) == 0) ok[t >> 5] = (m == 0xFFFFFFFFu);
    __syncthreads();
    if (t == 0) g_is64 = ok[0] & ok[1];
}

__device__ __forceinline__ int load_idx(const void* p, long long i) {
    if (g_is64) return (int)((const long long*)p)[i];
    return ((const int*)p)[i];
}

// ---------------- degree count (2 edges / thread, vector loads) ----------------
__global__ void k_deg(const void* ei) {
    int t = blockIdx.x * blockDim.x + threadIdx.x;
    if (t >= N_EDGES / 2) return;
    int d0, d1;
    if (g_is64) {
        longlong2 p = __ldg(&((const longlong2*)ei)[N_EDGES / 2 + t]);
        d0 = (int)p.x; d1 = (int)p.y;
    } else {
        int2 p = __ldg(&((const int2*)ei)[N_EDGES / 2 + t]);
        d0 = p.x; d1 = p.y;
    }
    atomicAdd(&g_deg[d0], 1);
    atomicAdd(&g_deg[d1], 1);
}

// ---------------- fused scan: g_off[v]=segment start, g_dinv ----------------
__global__ void k_scan() {
    int tid = threadIdx.x;
    int i = blockIdx.x * SCAN_CHUNK + tid;
    int lane = tid & 31, wid = tid >> 5;          // 16 warps
    int d = (i < N_NODES) ? g_deg[i] : 0;
    int v = d;
    #pragma unroll
    for (int o = 1; o < 32; o <<= 1) {
        int t = __shfl_up_sync(0xFFFFFFFFu, v, o);
        if (lane >= o) v += t;
    }
    __shared__ int ws[16];
    __shared__ int base;
    if (lane == 31) ws[wid] = v;
    __syncthreads();
    if (wid == 0) {
        int s = (lane < 16) ? ws[lane] : 0;
        int sv = s;
        #pragma unroll
        for (int o = 1; o < 16; o <<= 1) {
            int t = __shfl_up_sync(0xFFFFFFFFu, sv, o);
            if (lane >= o) sv += t;
        }
        if (lane < 16) ws[lane] = sv - s;          // exclusive warp offsets
        if (lane == 15) base = atomicAdd(&g_deg[N_NODES], sv);
    }
    __syncthreads();
    if (i < N_NODES) {
        g_off[i] = base + ws[wid] + (v - d);
        g_dinv[i] = rsqrtf((float)(d + 1));        // +1 self loop
    }
}

// ---------------- CSR fill (2 edges / thread): g_off start -> end ----------------
__global__ void k_fill(const void* ei) {
    int t = blockIdx.x * blockDim.x + threadIdx.x;
    if (t >= N_EDGES / 2) return;
    int s0, s1, d0, d1;
    if (g_is64) {
        longlong2 ps = __ldg(&((const longlong2*)ei)[t]);
        longlong2 pd = __ldg(&((const longlong2*)ei)[N_EDGES / 2 + t]);
        s0 = (int)ps.x; s1 = (int)ps.y; d0 = (int)pd.x; d1 = (int)pd.y;
    } else {
        int2 ps = __ldg(&((const int2*)ei)[t]);
        int2 pd = __ldg(&((const int2*)ei)[N_EDGES / 2 + t]);
        s0 = ps.x; s1 = ps.y; d0 = pd.x; d1 = pd.y;
    }
    int p0 = atomicAdd(&g_off[d0], 1);
    g_csr[p0] = s0;
    int p1 = atomicAdd(&g_off[d1], 1);
    g_csr[p1] = s1;
}

// ---------------- layer-1: g0 = fp16( dinv * (x @ W1) ), warp/node ----------------
__global__ void k_xw1(const float* __restrict__ x, const float* __restrict__ W1,
                      __half* __restrict__ outh) {
    int warp = (blockIdx.x * blockDim.x + threadIdx.x) >> 5;
    int lane = threadIdx.x & 31;
    int nwarps = (gridDim.x * blockDim.x) >> 5;
    const float4* W4 = (const float4*)W1;
    float4 w0 = __ldg(&W4[0 * 32 + lane]);
    float4 w1 = __ldg(&W4[1 * 32 + lane]);
    float4 w2 = __ldg(&W4[2 * 32 + lane]);
    float4 w3 = __ldg(&W4[3 * 32 + lane]);
    for (int vtx = warp; vtx < N_NODES; vtx += nwarps) {
        float xv = (lane < IN_C) ? __ldg(&x[vtx * IN_C + lane]) : 0.0f;
        float x0 = __shfl_sync(0xFFFFFFFFu, xv, 0);
        float x1 = __shfl_sync(0xFFFFFFFFu, xv, 1);
        float x2 = __shfl_sync(0xFFFFFFFFu, xv, 2);
        float x3 = __shfl_sync(0xFFFFFFFFu, xv, 3);
        float dv = g_dinv[vtx];
        float ax = dv * (x0 * w0.x + x1 * w1.x + x2 * w2.x + x3 * w3.x);
        float ay = dv * (x0 * w0.y + x1 * w1.y + x2 * w2.y + x3 * w3.y);
        float az = dv * (x0 * w0.z + x1 * w1.z + x2 * w2.z + x3 * w3.z);
        float aw = dv * (x0 * w0.w + x1 * w1.w + x2 * w2.w + x3 * w3.w);
        __half2 p0 = __floats2half2_rn(ax, ay);
        __half2 p1 = __floats2half2_rn(az, aw);
        uint2 u;
        u.x = *(const unsigned*)&p0;
        u.y = *(const unsigned*)&p1;
        ((uint2*)(outh + (size_t)vtx * HID))[lane] = u;
    }
}

// ---------------- fp16 gather: LDG.128, 16 lanes/edge, 2 edges/warp-load ----------------
__device__ __forceinline__ void acc8(float* a, uint4 u) {
    float2 f0 = __half22float2(*(const __half2*)&u.x);
    float2 f1 = __half22float2(*(const __half2*)&u.y);
    float2 f2 = __half22float2(*(const __half2*)&u.z);
    float2 f3 = __half22float2(*(const __half2*)&u.w);
    a[0] += f0.x; a[1] += f0.y; a[2] += f1.x; a[3] += f1.y;
    a[4] += f2.x; a[5] += f2.y; a[6] += f3.x; a[7] += f3.y;
}

__global__ void k_gather(const __half* __restrict__ gin, const float* __restrict__ bias,
                         __half* __restrict__ gout) {
    int warp = (blockIdx.x * blockDim.x + threadIdx.x) >> 5;
    int lane = threadIdx.x & 31;
    if (warp >= N_NODES) return;
    int v = warp;
    int hf = lane >> 4, sub = lane & 15;
    const uint4* gin4 = (const uint4*)gin;     // 16 uint4 per node row
    float a[8];
    #pragma unroll
    for (int k = 0; k < 8; ++k) a[k] = 0.0f;
    int e = g_off[v];                          // end (post-fill)
    int j = e - g_deg[v] + hf;                 // this half's first edge
    // 4 edges per half per iteration => 8 edges / warp, 2KB in flight
    for (; j + 6 < e; j += 8) {
        int s0 = __ldg(&g_csr[j]);
        int s1 = __ldg(&g_csr[j + 2]);
        int s2 = __ldg(&g_csr[j + 4]);
        int s3 = __ldg(&g_csr[j + 6]);
        uint4 u0 = __ldg(&gin4[(size_t)s0 * 16 + sub]);
        uint4 u1 = __ldg(&gin4[(size_t)s1 * 16 + sub]);
        uint4 u2 = __ldg(&gin4[(size_t)s2 * 16 + sub]);
        uint4 u3 = __ldg(&gin4[(size_t)s3 * 16 + sub]);
        acc8(a, u0); acc8(a, u1); acc8(a, u2); acc8(a, u3);
    }
    for (; j < e; j += 2) {
        int s0 = __ldg(&g_csr[j]);
        uint4 u0 = __ldg(&gin4[(size_t)s0 * 16 + sub]);
        acc8(a, u0);
    }
    __syncwarp();
    #pragma unroll
    for (int k = 0; k < 8; ++k) a[k] += __shfl_xor_sync(0xFFFFFFFFu, a[k], 16);
    if (hf == 0) {
        uint4 us = __ldg(&gin4[(size_t)v * 16 + sub]);   // self loop
        acc8(a, us);
        float dv = g_dinv[v];
        const float4* b4 = (const float4*)bias;
        float4 bb0 = __ldg(&b4[sub * 2]);
        float4 bb1 = __ldg(&b4[sub * 2 + 1]);
        __half2 p0 = __floats2half2_rn(fmaxf(dv * a[0] + bb0.x, 0.0f),
                                       fmaxf(dv * a[1] + bb0.y, 0.0f));
        __half2 p1 = __floats2half2_rn(fmaxf(dv * a[2] + bb0.z, 0.0f),
                                       fmaxf(dv * a[3] + bb0.w, 0.0f));
        __half2 p2 = __floats2half2_rn(fmaxf(dv * a[4] + bb1.x, 0.0f),
                                       fmaxf(dv * a[5] + bb1.y, 0.0f));
        __half2 p3 = __floats2half2_rn(fmaxf(dv * a[6] + bb1.z, 0.0f),
                                       fmaxf(dv * a[7] + bb1.w, 0.0f));
        uint4 o;
        o.x = *(const unsigned*)&p0;
        o.y = *(const unsigned*)&p1;
        o.z = *(const unsigned*)&p2;
        o.w = *(const unsigned*)&p3;
        ((uint4*)gout)[(size_t)v * 16 + sub] = o;
    }
}

// ---------------- tensor-core GEMM: g2 = fp16( dinv * (h2 @ W2) ) ----------------
#define MM_PITCH 136
__global__ void k_h2w2_mma(const __half* __restrict__ hin, const float* __restrict__ W2,
                           __half* __restrict__ outh) {
    extern __shared__ __half smh[];
    __half* W2h = smh;                                   // [128][MM_PITCH] fp16
    float* stage = (float*)(smh + HID * MM_PITCH);       // [8][16][MM_PITCH] fp32
    int t = threadIdx.x;
    int warp = t >> 5, lane = t & 31;
    for (int i = t; i < HID * HID; i += 256) {
        int r = i >> 7, c = i & 127;
        W2h[r * MM_PITCH + c] = __float2half(W2[i]);
    }
    __syncthreads();

    float* st = stage + warp * 16 * MM_PITCH;
    const int ntiles = N_PAD / 128;   // 782
    for (int tile = blockIdx.x; tile < ntiles; tile += gridDim.x) {
        int row0 = tile * 128 + warp * 16;
        wmma::fragment<wmma::accumulator, 16, 16, 16, float> c[8];
        #pragma unroll
        for (int n = 0; n < 8; ++n) wmma::fill_fragment(c[n], 0.0f);
        #pragma unroll
        for (int k0 = 0; k0 < HID; k0 += 16) {
            wmma::fragment<wmma::matrix_a, 16, 16, 16, __half, wmma::row_major> a;
            wmma::load_matrix_sync(a, hin + (size_t)row0 * HID + k0, HID);
            #pragma unroll
            for (int n = 0; n < 8; ++n) {
                wmma::fragment<wmma::matrix_b, 16, 16, 16, __half, wmma::row_major> b;
                wmma::load_matrix_sync(b, W2h + k0 * MM_PITCH + n * 16, MM_PITCH);
                wmma::mma_sync(c[n], a, b, c[n]);
            }
        }
        #pragma unroll
        for (int n = 0; n < 8; ++n)
            wmma::store_matrix_sync(st + n * 16, c[n], MM_PITCH, wmma::mem_row_major);
        __syncwarp();
        #pragma unroll
        for (int r = 0; r < 16; ++r) {
            int row = row0 + r;
            if (row < N_NODES) {
                float dv = g_dinv[row];
                float4 v = *(const float4*)&st[r * MM_PITCH + lane * 4];
                __half2 p0 = __floats2half2_rn(dv * v.x, dv * v.y);
                __half2 p1 = __floats2half2_rn(dv * v.z, dv * v.w);
                uint2 u;
                u.x = *(const unsigned*)&p0;
                u.y = *(const unsigned*)&p1;
                *(uint2*)&outh[(size_t)row * HID + lane * 4] = u;
            }
        }
        __syncwarp();
    }
}

// ---------------- fused pool: bounds + mean, one block per graph ----------------
__global__ void k_poolmean(const __half* __restrict__ h, const void* batch,
                           float* __restrict__ outp) {
    int g = blockIdx.x;
    __shared__ int sb[2];
    if (threadIdx.x < 2) {
        int target = g + threadIdx.x;
        int lo = 0, hi = N_NODES;
        while (lo < hi) {
            int mid = (lo + hi) >> 1;
            if (load_idx(batch, mid) < target) lo = mid + 1; else hi = mid;
        }
        sb[threadIdx.x] = lo;
    }
    __syncthreads();
    int s = sb[0], e = sb[1];
    int stream = threadIdx.x >> 6;     // 16 row streams
    int c2 = threadIdx.x & 63;         // half2 column
    const __half2* h2p = (const __half2*)h;
    float2 acc = make_float2(0.0f, 0.0f);
    #pragma unroll 4
    for (int r = s + stream; r < e; r += 16) {
        float2 t = __half22float2(h2p[(size_t)r * 64 + c2]);
        acc.x += t.x; acc.y += t.y;
    }
    __shared__ float2 red[1024];
    red[threadIdx.x] = acc;
    __syncthreads();
    if (threadIdx.x < 64) {
        float2 a = make_float2(0.0f, 0.0f);
        #pragma unroll
        for (int k = 0; k < 16; ++k) {
            float2 t = red[k * 64 + threadIdx.x];
            a.x += t.x; a.y += t.y;
        }
        float inv = 1.0f / fmaxf((float)(e - s), 1.0f);
        outp[g * HID + c2 * 2]     = a.x * inv;
        outp[g * HID + c2 * 2 + 1] = a.y * inv;
    }
}

// ---------------- launch ----------------
extern "C" void kernel_launch(void* const* d_in, const int* in_sizes, int n_in,
                              void* d_out, int out_size) {
    const float* x  = (const float*)d_in[0];
    const void*  ei = d_in[1];
    const void*  batch = d_in[2];
    const float* W1 = (const float*)d_in[3];
    const float* b1 = (const float*)d_in[4];
    const float* W2 = (const float*)d_in[5];
    const float* b2 = (const float*)d_in[6];
    float* out = (float*)d_out;

    void* degp;  cudaGetSymbolAddress(&degp, g_deg);
    void* h16Ap; cudaGetSymbolAddress(&h16Ap, g_h16A);
    void* h16Bp; cudaGetSymbolAddress(&h16Bp, g_h16B);

    static int smem_set = 0;
    const int mma_smem = HID * MM_PITCH * sizeof(__half) + 8 * 16 * MM_PITCH * sizeof(float);
    if (!smem_set) {
        cudaFuncSetAttribute(k_h2w2_mma, cudaFuncAttributeMaxDynamicSharedMemorySize, mma_smem);
        smem_set = 1;
    }

    k_detect<<<1, 64>>>((const int*)ei);
    cudaMemsetAsync(degp, 0, (N_NODES + 1) * sizeof(int));

    const int EB2 = (N_EDGES / 2 + 255) / 256;
    k_deg<<<EB2, 256>>>(ei);
    k_scan<<<SCAN_BLKS, SCAN_CHUNK>>>();
    k_fill<<<EB2, 256>>>(ei);

    k_xw1<<<256, 256>>>(x, W1, (__half*)h16Ap);                                        // g0 -> A
    k_gather<<<(N_NODES * 32 + 255) / 256, 256>>>((__half*)h16Ap, b1, (__half*)h16Bp); // h2 -> B
    k_h2w2_mma<<<296, 256, mma_smem>>>((__half*)h16Bp, W2, (__half*)h16Ap);            // g2 -> A
    k_gather<<<(N_NODES * 32 + 255) / 256, 256>>>((__half*)h16Ap, b2, (__half*)h16Bp); // h3 -> B

    k_poolmean<<<N_GRAPH, 1024>>>((__half*)h16Bp, batch, out);
}